// round 12
// baseline (speedup 1.0000x reference)
#include <cuda_runtime.h>

// Problem constants: H=64, M=N=128, k=9, w=3
#define PTOT (64 * 128 * 128)
#define KNN  9

// Tile: 16 x 4 x 4 voxels per block; code/value halo 18 x 6 x 6
#define TX 16
#define TY 4
#define TZ 4
#define HX 18
#define HY 6
#define HROWS (HX * HY * 6)     // 648
#define HXY (HX * HY)           // 108

// pass2 anat halo (neighbors-of-neighbors): 20 x 8 x 8
#define AX 20
#define AXY 160
#define AROWS (AX * 8 * 8)      // 1280

// Scratch: ONLY codes — one uint4 per voxel, 9 code bytes in .x/.y/.z
// (byte = (oz<<4)|(oy<<2)|ox, offsets in 0..2), .w unused. 16.8 MB.
__device__ uint4 g_code4[PTOT];

// ---------------------------------------------------------------------------
// Pass 1: stable top-9 of 27 periodic window neighbors by |v - center|,
// via a Batcher odd-even merge sorting network on 32 u64 keys:
//   key = (abs-dist bits << 32) | code_byte
// code_byte = (oz<<4)|(oy<<2)|ox is STRICTLY MONOTONE in the column index c,
// so ascending u64 order == JAX stable argsort order (ties -> lower column).
// 5 sentinel keys (= ~0ull) const-fold; only positions 0..8 are read, so the
// compiler dead-codes every comparator not feeding the top 9.
// Output: 9 code bytes per voxel, written coalesced as uint4 from registers.
// ---------------------------------------------------------------------------
__global__ __launch_bounds__(256) void pass1_kernel(const float* __restrict__ anat) {
    __shared__ float s_anat[HROWS];

    int tid = threadIdx.x;
    int lx = tid & 15, ly = (tid >> 4) & 3, lz = tid >> 6;
    int x0 = blockIdx.x * TX, y0 = blockIdx.y * TY, z0 = blockIdx.z * TZ;

    for (int t = tid; t < HROWS; t += 256) {
        int hx = t % HX; int r = t / HX; int hy = r % HY; int hz = r / HY;
        int gx = (x0 + hx + 127) & 127;
        int gy = (y0 + hy + 127) & 127;
        int gz = (z0 + hz + 63) & 63;
        s_anat[t] = __ldg(&anat[(gz << 14) | (gy << 7) | gx]);
    }
    __syncthreads();

    int center = (lz + 1) * HXY + (ly + 1) * HX + (lx + 1);
    float ac = s_anat[center];

    unsigned long long key[32];
#pragma unroll
    for (int oz = 0; oz < 3; ++oz)
#pragma unroll
        for (int oy = 0; oy < 3; ++oy)
#pragma unroll
            for (int ox = 0; ox < 3; ++ox) {
                int c = oz * 9 + oy * 3 + ox;
                float v = s_anat[center + (oz - 1) * HXY + (oy - 1) * HX + (ox - 1)];
                unsigned db = __float_as_uint(fabsf(v - ac));   // >=0: int order == float order
                key[c] = ((unsigned long long)db << 32)
                       | (unsigned)((oz << 4) | (oy << 2) | ox);
            }
#pragma unroll
    for (int c = 27; c < 32; ++c) key[c] = ~0ull;   // sentinels (const-fold)

    // Batcher odd-even merge sort, n = 32 (Sedgewick iterative form).
#pragma unroll
    for (int p = 1; p < 32; p <<= 1)
#pragma unroll
        for (int k = p; k > 0; k >>= 1)
#pragma unroll
            for (int j = k % p; j + k < 32; j += 2 * k)
#pragma unroll
                for (int i = 0; i < k; ++i)
                    if ((i + j) / (2 * p) == (i + j + k) / (2 * p)) {
                        unsigned long long a = key[i + j], b = key[i + j + k];
                        bool sw = b < a;
                        key[i + j]     = sw ? b : a;
                        key[i + j + k] = sw ? a : b;
                    }

    // Pack the 9 winning code bytes (key lo bytes, rank order) into 3 words.
    unsigned b0 = (unsigned)key[0] & 0xffu, b1 = (unsigned)key[1] & 0xffu;
    unsigned b2 = (unsigned)key[2] & 0xffu, b3 = (unsigned)key[3] & 0xffu;
    unsigned b4 = (unsigned)key[4] & 0xffu, b5 = (unsigned)key[5] & 0xffu;
    unsigned b6 = (unsigned)key[6] & 0xffu, b7 = (unsigned)key[7] & 0xffu;
    unsigned b8 = (unsigned)key[8] & 0xffu;
    unsigned w0 = b0 | (b1 << 8) | (b2 << 16) | (b3 << 24);
    unsigned w1 = b4 | (b5 << 8) | (b6 << 16) | (b7 << 24);
    unsigned w2 = b8;

    int i = ((z0 + lz) << 14) | ((y0 + ly) << 7) | (x0 + lx);
    g_code4[i] = make_uint4(w0, w1, w2, 0u);    // coalesced
}

// ---------------------------------------------------------------------------
// Pass 2 (exact R11 version — measured 52.9us): rebuild the 648 value rows in
// smem (scalar stride 9; gcd(9,32)=1 -> divergent reads near conflict-free)
// from a 20x8x8 anat halo + one LDG.128 of codes per row.
// Output staged through s9, written back as float4 (coalesced).
// ---------------------------------------------------------------------------
__global__ __launch_bounds__(256) void pass2_kernel(const float* __restrict__ anat,
                                                    const float* __restrict__ ksig,
                                                    float* __restrict__ out) {
    __shared__ __align__(16) float s9[HROWS * 9];   // 23328 B, reused for out staging
    __shared__ float s_a[AROWS];                    // 5120 B anat halo

    int tid = threadIdx.x;
    int lx = tid & 15, ly = (tid >> 4) & 3, lz = tid >> 6;
    int x0 = blockIdx.x * TX, y0 = blockIdx.y * TY, z0 = blockIdx.z * TZ;

    // anat halo 20x8x8 centered on tile (offset -2): 5 loads/thread.
    for (int t = tid; t < AROWS; t += 256) {
        int ax = t % AX; int r = t / AX; int ay = r & 7; int az = r >> 3;
        int gx = (x0 + ax + 126) & 127;
        int gy = (y0 + ay + 126) & 127;
        int gz = (z0 + az + 62) & 63;
        s_a[t] = __ldg(&anat[(gz << 14) | (gy << 7) | gx]);
    }

    int i = ((z0 + lz) << 14) | ((y0 + ly) << 7) | (x0 + lx);
    uint4 cwv = g_code4[i];
    unsigned cw[3] = { cwv.x, cwv.y, cwv.z };
    float ks = __ldg(&ksig[0]);
    __syncthreads();

    // Build the 648 value rows: decode 9 codes per row, gather from s_a.
    for (int row = tid; row < HROWS; row += 256) {
        int hx = row % HX; int r = row / HX; int hy = r % HY; int hz = r / HY;
        int gx = (x0 + hx + 127) & 127;
        int gy = (y0 + hy + 127) & 127;
        int gz = (z0 + hz + 63) & 63;
        uint4 w = g_code4[(gz << 14) | (gy << 7) | gx];
        unsigned ws[3] = { w.x, w.y, w.z };
        int ac = (hz + 1) * AXY + (hy + 1) * AX + (hx + 1) - (AXY + AX + 1);
        float* d = &s9[row * 9];
#pragma unroll
        for (int t = 0; t < 9; ++t) {
            unsigned c = (ws[t >> 2] >> ((t & 3) * 8)) & 0xffu;
            int off = (int)(c >> 4) * AXY + (int)((c >> 2) & 3) * AX + (int)(c & 3);
            d[t] = s_a[ac + off];
        }
    }
    __syncthreads();

    int center = (lz + 1) * HXY + (ly + 1) * HX + (lx + 1) - (HXY + HX + 1);
    float wi[KNN];
#pragma unroll
    for (int t = 0; t < KNN; ++t) wi[t] = s9[(center + (HXY + HX + 1)) * 9 + t];

    // sigma = std(Wk, ddof=1), two-pass for fp32 stability
    float sum = 0.f;
#pragma unroll
    for (int t = 0; t < KNN; ++t) sum += wi[t];
    float mean = sum * (1.0f / 9.0f);
    float var = 0.f;
#pragma unroll
    for (int t = 0; t < KNN; ++t) { float d = wi[t] - mean; var += d * d; }
    var *= (1.0f / 8.0f);
    float sigma = sqrtf(var);
    bool  zeroSig = (sigma == 0.0f);
    float sig = zeroSig ? 1.0f : sigma;

    // logits = -(||diff|| / sigma / (sqrt(2)*ks))^2 = -s / (2*sigma^2*ks^2)
    float inv = 1.0f / (2.0f * sig * sig * ks * ks);

    float wie[KNN];
#pragma unroll
    for (int t = 0; t < KNN; ++t) wie[t] = wi[t] + 1e-6f;

    float logits[KNN];
#pragma unroll
    for (int j = 0; j < KNN; ++j) {
        int c = (int)((cw[j >> 2] >> ((j & 3) * 8)) & 0xffu);
        int rowc = center + (c >> 4) * HXY + ((c >> 2) & 3) * HX + (c & 3);
        const float* nr = &s9[rowc * 9];
        float s = 0.f;
#pragma unroll
        for (int t = 0; t < KNN; ++t) {
            float df = wie[t] - nr[t];
            s = fmaf(df, df, s);
        }
        logits[j] = zeroSig ? 0.0f : -(s * inv);
    }

    // softmax over the 9 neighbors
    float mx = logits[0];
#pragma unroll
    for (int j = 1; j < KNN; ++j) mx = fmaxf(mx, logits[j]);
    float e[KNN], se = 0.f;
#pragma unroll
    for (int j = 0; j < KNN; ++j) { e[j] = __expf(logits[j] - mx); se += e[j]; }
    float rse = 1.0f / se;

    __syncthreads();                       // all s9 reads done; reuse buffer
#pragma unroll
    for (int j = 0; j < KNN; ++j) s9[tid * KNN + j] = e[j] * rse;
    __syncthreads();

    // Coalesced out: 16 lines x 144 floats = 36 float4 per line, 576 total.
    float4* s_out4 = (float4*)s9;
    for (int q = tid; q < 576; q += 256) {
        int line = q / 36, off = q - line * 36;
        int llz = line >> 2, lly = line & 3;
        int vox = ((z0 + llz) << 14) | ((y0 + lly) << 7) | x0;
        ((float4*)(out + (size_t)vox * KNN))[off] = s_out4[q];
    }
}

extern "C" void kernel_launch(void* const* d_in, const int* in_sizes, int n_in,
                              void* d_out, int out_size) {
    const float* anat = (const float*)d_in[0];
    const float* ksig = (const float*)d_in[1];
    float* out = (float*)d_out;

    dim3 grid(128 / TX, 128 / TY, 64 / TZ);   // 8 x 32 x 16 = 4096 blocks
    pass1_kernel<<<grid, 256>>>(anat);
    pass2_kernel<<<grid, 256>>>(anat, ksig, out);
}

// round 13
// speedup vs baseline: 2.4555x; 2.4555x over previous
#include <cuda_runtime.h>

// Problem constants: H=64, M=N=128, k=9, w=3
#define PTOT (64 * 128 * 128)
#define KNN  9

// ---- pass1 tile: 16 x 4 x 4; halo 18 x 6 x 6 ----
#define TX 16
#define TY 4
#define TZ 4
#define HX 18
#define HY 6
#define HROWS (HX * HY * 6)     // 648
#define HXY (HX * HY)           // 108

// ---- pass2 tile: 16 x 8 x 4, 512 threads; value-row halo 18 x 10 x 6 ----
#define TY2 8
#define H2XY (18 * 10)          // 180
#define H2ROWS (18 * 10 * 6)    // 1080
// pass2 anat halo: 20 x 12 x 8
#define A2X 20
#define A2XY 240
#define A2ROWS (A2X * 12 * 8)   // 1920

// Scratch: ONLY codes — one uint4 per voxel, 9 code bytes in .x/.y/.z
// (byte = (oz<<4)|(oy<<2)|ox, offsets in 0..2), .w unused. 16.8 MB.
__device__ uint4 g_code4[PTOT];

// ---------------------------------------------------------------------------
// Pass 1 (exact R11 version — measured ~62us): stable top-9 of 27 periodic
// window neighbors by |v - center|.
//   rank(c) = #{j<c: d_j <= d_c} + #{j>c: d_j < d_c}
// Branchless fixed-latency pair bodies: pre-add the c-side at compile time
// (init_c = c), then p = sign(bits(d_c) - bits(d_j)); rank_j += p*Wj;
// rank_c -= p*Wc. Integer compares on abs-bit patterns (order == float order
// for d >= 0). Center candidate 13 folded. Ranks byte-packed 4-per-u32.
// ---------------------------------------------------------------------------
__global__ __launch_bounds__(256) void pass1_kernel(const float* __restrict__ anat) {
    __shared__ float s_anat[HROWS];
    __shared__ uint4 s_code4[256];

    int tid = threadIdx.x;
    int lx = tid & 15, ly = (tid >> 4) & 3, lz = tid >> 6;
    int x0 = blockIdx.x * TX, y0 = blockIdx.y * TY, z0 = blockIdx.z * TZ;

    for (int t = tid; t < HROWS; t += 256) {
        int hx = t % HX; int r = t / HX; int hy = r % HY; int hz = r / HY;
        int gx = (x0 + hx + 127) & 127;
        int gy = (y0 + hy + 127) & 127;
        int gz = (z0 + hz + 63) & 63;
        s_anat[t] = __ldg(&anat[(gz << 14) | (gy << 7) | gx]);
    }
    __syncthreads();

    int center = (lz + 1) * HXY + (ly + 1) * HX + (lx + 1);
    float ac = s_anat[center];

    int di[27];
#pragma unroll
    for (int oz = 0; oz < 3; ++oz)
#pragma unroll
        for (int oy = 0; oy < 3; ++oy)
#pragma unroll
            for (int ox = 0; ox < 3; ++ox) {
                int c = oz * 9 + oy * 3 + ox;
                float v = s_anat[center + (oz - 1) * HXY + (oy - 1) * HX + (ox - 1)];
                di[c] = (int)(__float_as_uint(v - ac) & 0x7fffffffu);
            }

    unsigned ri[7] = { 0x03020100u, 0x07060504u, 0x0B0A0908u, 0x0F0E0D0Cu,
                       0x13121110u, 0x17161514u, 0x001A1918u };

#pragma unroll
    for (int j = 0; j < 13; ++j) {
        unsigned p = ((unsigned)(-di[j])) >> 31;
        ri[j >> 2] += p * (1u << ((j & 3) * 8));
        ri[3]      -= p * (1u << 8);
    }

#pragma unroll
    for (int o = 1; o < 27; ++o)
#pragma unroll
        for (int j = 0; j + o < 27; ++j) {
            const int c = j + o;
            if (j == 13 || c == 13) continue;
            unsigned p = ((unsigned)(di[c] - di[j])) >> 31;   // d_j > d_c
            ri[j >> 2] += p * (1u << ((j & 3) * 8));
            ri[c >> 2] -= p * (1u << ((c & 3) * 8));
        }

    unsigned char* scb = (unsigned char*)s_code4;
#pragma unroll
    for (int c = 0; c < 27; ++c) {
        int r = (int)((ri[c >> 2] >> ((c & 3) * 8)) & 255u);
        if (r < KNN) {
            int oz = c / 9, rem = c - 9 * oz, oy = rem / 3, ox = rem - 3 * oy; // compile-time
            scb[tid * 16 + r] = (unsigned char)((oz << 4) | (oy << 2) | ox);
        }
    }
    __syncthreads();

    {
        int line = tid >> 4, off = tid & 15;
        int llz = line >> 2, lly = line & 3;
        int vox = ((z0 + llz) << 14) | ((y0 + lly) << 7) | (x0 + off);
        g_code4[vox] = s_code4[tid];
    }
}

// ---------------------------------------------------------------------------
// Pass 2: 512 threads, 16x8x4 tile (rebuild redundancy 2.11 vs 2.53).
// Rebuild the 1080 value rows in smem (scalar stride 9; gcd(9,32)=1 ->
// divergent reads near conflict-free) from a 20x12x8 anat halo + one LDG.128
// of codes per row. 46.6 KB smem, 4 blocks/SM = 64 warps (100% occ).
// Output staged through s9, written back as float4 (coalesced).
// ---------------------------------------------------------------------------
__global__ __launch_bounds__(512) void pass2_kernel(const float* __restrict__ anat,
                                                    const float* __restrict__ ksig,
                                                    float* __restrict__ out) {
    __shared__ __align__(16) float s9[H2ROWS * 9];  // 38880 B, reused for out staging
    __shared__ float s_a[A2ROWS];                   // 7680 B anat halo

    int tid = threadIdx.x;
    int lx = tid & 15, ly = (tid >> 4) & 7, lz = tid >> 7;
    int x0 = blockIdx.x * TX, y0 = blockIdx.y * TY2, z0 = blockIdx.z * TZ;

    // anat halo 20x12x8 (offset -2): up to 4 loads/thread.
    for (int t = tid; t < A2ROWS; t += 512) {
        int ax = t % A2X; int r = t / A2X; int ay = r % 12; int az = r / 12;
        int gx = (x0 + ax + 126) & 127;
        int gy = (y0 + ay + 126) & 127;
        int gz = (z0 + az + 62) & 63;
        s_a[t] = __ldg(&anat[(gz << 14) | (gy << 7) | gx]);
    }

    int i = ((z0 + lz) << 14) | ((y0 + ly) << 7) | (x0 + lx);
    uint4 cwv = g_code4[i];
    unsigned cw[3] = { cwv.x, cwv.y, cwv.z };
    float ks = __ldg(&ksig[0]);
    __syncthreads();

    // Build the 1080 value rows: decode 9 codes per row, gather from s_a.
    for (int row = tid; row < H2ROWS; row += 512) {
        int hx = row % 18; int r = row / 18; int hy = r % 10; int hz = r / 10;
        int gx = (x0 + hx + 127) & 127;
        int gy = (y0 + hy + 127) & 127;
        int gz = (z0 + hz + 63) & 63;
        uint4 w = g_code4[(gz << 14) | (gy << 7) | gx];
        unsigned ws[3] = { w.x, w.y, w.z };
        // row (hx,hy,hz) sits at anat-halo coords (hx+1,hy+1,hz+1); code
        // offsets are (oz-1,oy-1,ox-1) -> pre-subtract.
        int ac = (hz + 1) * A2XY + (hy + 1) * A2X + (hx + 1) - (A2XY + A2X + 1);
        float* d = &s9[row * 9];
#pragma unroll
        for (int t = 0; t < 9; ++t) {
            unsigned c = (ws[t >> 2] >> ((t & 3) * 8)) & 0xffu;
            int off = (int)(c >> 4) * A2XY + (int)((c >> 2) & 3) * A2X + (int)(c & 3);
            d[t] = s_a[ac + off];
        }
    }
    __syncthreads();

    int center = (lz + 1) * H2XY + (ly + 1) * 18 + (lx + 1) - (H2XY + 18 + 1);
    float wi[KNN];
#pragma unroll
    for (int t = 0; t < KNN; ++t) wi[t] = s9[(center + (H2XY + 18 + 1)) * 9 + t];

    // sigma = std(Wk, ddof=1), two-pass for fp32 stability
    float sum = 0.f;
#pragma unroll
    for (int t = 0; t < KNN; ++t) sum += wi[t];
    float mean = sum * (1.0f / 9.0f);
    float var = 0.f;
#pragma unroll
    for (int t = 0; t < KNN; ++t) { float d = wi[t] - mean; var += d * d; }
    var *= (1.0f / 8.0f);
    float sigma = sqrtf(var);
    bool  zeroSig = (sigma == 0.0f);
    float sig = zeroSig ? 1.0f : sigma;

    // logits = -(||diff|| / sigma / (sqrt(2)*ks))^2 = -s / (2*sigma^2*ks^2)
    float inv = 1.0f / (2.0f * sig * sig * ks * ks);

    float wie[KNN];
#pragma unroll
    for (int t = 0; t < KNN; ++t) wie[t] = wi[t] + 1e-6f;

    float logits[KNN];
#pragma unroll
    for (int j = 0; j < KNN; ++j) {
        int c = (int)((cw[j >> 2] >> ((j & 3) * 8)) & 0xffu);
        int rowc = center + (c >> 4) * H2XY + ((c >> 2) & 3) * 18 + (c & 3);
        const float* nr = &s9[rowc * 9];
        float s = 0.f;
#pragma unroll
        for (int t = 0; t < KNN; ++t) {
            float df = wie[t] - nr[t];
            s = fmaf(df, df, s);
        }
        logits[j] = zeroSig ? 0.0f : -(s * inv);
    }

    // softmax over the 9 neighbors
    float mx = logits[0];
#pragma unroll
    for (int j = 1; j < KNN; ++j) mx = fmaxf(mx, logits[j]);
    float e[KNN], se = 0.f;
#pragma unroll
    for (int j = 0; j < KNN; ++j) { e[j] = __expf(logits[j] - mx); se += e[j]; }
    float rse = 1.0f / se;

    __syncthreads();                       // all s9 reads done; reuse buffer
#pragma unroll
    for (int j = 0; j < KNN; ++j) s9[tid * KNN + j] = e[j] * rse;
    __syncthreads();

    // Coalesced out: 32 lines x 144 floats = 36 float4 per line, 1152 total.
    float4* s_out4 = (float4*)s9;
    for (int q = tid; q < 1152; q += 512) {
        int line = q / 36, off = q - line * 36;
        int llz = line >> 3, lly = line & 7;
        int vox = ((z0 + llz) << 14) | ((y0 + lly) << 7) | x0;
        ((float4*)(out + (size_t)vox * KNN))[off] = s_out4[q];
    }
}

extern "C" void kernel_launch(void* const* d_in, const int* in_sizes, int n_in,
                              void* d_out, int out_size) {
    const float* anat = (const float*)d_in[0];
    const float* ksig = (const float*)d_in[1];
    float* out = (float*)d_out;

    dim3 grid1(128 / TX, 128 / TY, 64 / TZ);    // 4096 blocks
    pass1_kernel<<<grid1, 256>>>(anat);
    dim3 grid2(128 / TX, 128 / TY2, 64 / TZ);   // 8 x 16 x 16 = 2048 blocks
    pass2_kernel<<<grid2, 512>>>(anat, ksig, out);
}